// round 14
// baseline (speedup 1.0000x reference)
#include <cuda_runtime.h>
#include <cuda_fp16.h>
#include <cstdint>

// Problem dims
constexpr int kT  = 8192;
constexpr int kNS = 512;
constexpr int kNH = 1024;
constexpr int kNO = 512;
constexpr int kNG = 4 * kNH;  // 4096 gate rows

constexpr int kNumCTA = 128;                 // persistent CTAs (<148 SMs -> co-resident)
constexpr int kUnitsPerCTA = kNH / kNumCTA;  // 8 hidden units per CTA

// ---------------- scratch (static device allocations; no cudaMalloc) ----------------
__device__ float g_Z[(size_t)kT * kNG];    // 128 MB: layer-0 gate preactivations / logits
__device__ float g_H0[(size_t)kT * kNH];   // 32 MB (NaN-canary protocol)
__device__ float g_H1[(size_t)kT * kNH];   // 32 MB (NaN-canary protocol)

// ---------------- NaN prefill: data-as-signal canary ----------------
__global__ void prefill_nan(float4* a, int n4) {
    int i = blockIdx.x * blockDim.x + threadIdx.x;
    const float qn = __int_as_float(0x7FC00000);
    float4 v = make_float4(qn, qn, qn, qn);
    if (i < n4) a[i] = v;
}

// ---------------- fp32 tiled GEMM: C[M,N] = A[M,K] * B[N,K]^T (+bias1[n]+bias2[n]) ----
__global__ __launch_bounds__(256) void gemm_nt(
    const float* __restrict__ A, const float* __restrict__ B,
    const float* __restrict__ b1, const float* __restrict__ b2,
    float* __restrict__ C, int M, int N, int K)
{
    __shared__ float As[8][128];
    __shared__ float Bs[8][128];
    const int tid = threadIdx.x;
    const int m0 = blockIdx.y * 128;
    const int n0 = blockIdx.x * 128;
    const int ty = tid >> 4;
    const int tx = tid & 15;
    const int lrow = tid >> 1;
    const int lk = (tid & 1) * 4;
    const float* Ap = A + (size_t)(m0 + lrow) * K + lk;
    const float* Bp = B + (size_t)(n0 + lrow) * K + lk;

    float acc[8][8];
#pragma unroll
    for (int i = 0; i < 8; i++)
#pragma unroll
        for (int j = 0; j < 8; j++) acc[i][j] = 0.f;

    for (int k0 = 0; k0 < K; k0 += 8) {
        float4 av = *(const float4*)(Ap + k0);
        float4 bv = *(const float4*)(Bp + k0);
        As[lk + 0][lrow] = av.x; As[lk + 1][lrow] = av.y;
        As[lk + 2][lrow] = av.z; As[lk + 3][lrow] = av.w;
        Bs[lk + 0][lrow] = bv.x; Bs[lk + 1][lrow] = bv.y;
        Bs[lk + 2][lrow] = bv.z; Bs[lk + 3][lrow] = bv.w;
        __syncthreads();
#pragma unroll
        for (int kk = 0; kk < 8; kk++) {
            float a[8], b[8];
#pragma unroll
            for (int i = 0; i < 8; i++) a[i] = As[kk][i * 16 + ty];
#pragma unroll
            for (int j = 0; j < 8; j++) b[j] = Bs[kk][j * 16 + tx];
#pragma unroll
            for (int i = 0; i < 8; i++)
#pragma unroll
                for (int j = 0; j < 8; j++) acc[i][j] += a[i] * b[j];
        }
        __syncthreads();
    }

#pragma unroll
    for (int j = 0; j < 8; j++) {
        int n = n0 + j * 16 + tx;
        float bias = 0.f;
        if (b1) bias += b1[n];
        if (b2) bias += b2[n];
#pragma unroll
        for (int i = 0; i < 8; i++) {
            int m = m0 + i * 16 + ty;
            C[(size_t)m * N + n] = acc[i][j] + bias;
        }
    }
}

// ---- helpers: volatile data-as-signal loads/stores ----
__device__ __forceinline__ float4 ld_vol4(const float4* p) {
    float4 v;
    asm volatile("ld.volatile.global.v4.f32 {%0,%1,%2,%3}, [%4];"
                 : "=f"(v.x), "=f"(v.y), "=f"(v.z), "=f"(v.w) : "l"(p) : "memory");
    return v;
}
__device__ __forceinline__ void st_vol(float* p, float v) {
    asm volatile("st.volatile.global.f32 [%0], %1;" :: "l"(p), "f"(v) : "memory");
}
__device__ __forceinline__ bool ok4(float4 v) {
    return (v.x == v.x) & (v.y == v.y) & (v.z == v.z) & (v.w == v.w);
}

// ---------------- fused 2-layer persistent LSTM recurrence -------------------------
// Warp-per-unit layout: each warp owns ALL 4 gate rows of ONE hidden unit, so the
// shuffle reduce leaves all four gate dots in every lane -> in-warp activation and
// immediate publish (no 2nd barrier, no sDot exchange, no cross-warp gather).
// group A (warps 8-15, poller warp 15): layer 0, W_hh0 rows in REGISTERS.
// group B (warps 0-7,  poller warp 7):  layer 1, W_ih1 rows in REGISTERS,
//         W_hh1 in SMEM; warps 0-6 stage h0[e] (mailbox-guarded) in parallel with
//         warp 7's NaN-poll of h1[e-1].
// NaN-canary protocol for cross-CTA handoff (see R11). One bar per group per epoch;
// sH buffers are double-buffered by epoch parity (bar-protected).
__global__ __launch_bounds__(512) void lstm_fused(
    const float* __restrict__ Z0, const float* __restrict__ Whh0,
    const float* __restrict__ Wih1, const float* __restrict__ Whh1,
    const float* __restrict__ b_ih1, const float* __restrict__ b_hh1,
    float* H0, float* H1)
{
    extern __shared__ __half2 sW1h[];            // [32][512] half2 = 64 KB (W_hh1 only)
    __shared__ float sH0a[2][kNH];               // A: staged h0[e-1] (double buffer)
    __shared__ float sH0b[2][kNH];               // B: staged h0[e]
    __shared__ float sH1b[2][kNH];               // B: staged h1[e-1]
    __shared__ float sBias1[32];
    __shared__ int   sSeen;                      // mailbox: sSeen = e  <=>  h0[e-1] proven

    const int tid  = threadIdx.x;
    const int b    = blockIdx.x;
    const int warp = tid >> 5;
    const int lane = tid & 31;
    const uint32_t seenAddr = (uint32_t)__cvta_generic_to_shared(&sSeen);

    // ---- load + convert W_hh1 panel into SMEM (gate-major lr = g*8+u) ----
    for (int i = tid; i < 32 * 512; i += 512) {
        int lr = i >> 9, p = i & 511;
        int g = lr >> 3, u = lr & 7;
        const float2 wv = *(const float2*)(
            Whh1 + (size_t)(g * kNH + b * kUnitsPerCTA + u) * kNH + 2 * p);
        sW1h[i] = __floats2half2_rn(wv.x, wv.y);
    }
    if (tid < 32) {
        int g = tid >> 3, u = tid & 7;
        int idx = g * kNH + b * kUnitsPerCTA + u;
        sBias1[tid] = b_ih1[idx] + b_hh1[idx];
    }
    // zero both parity buffers of sH0a and sH1b (read at e=0)
    {
        float4 z4 = make_float4(0.f, 0.f, 0.f, 0.f);
        ((float4*)sH0a)[tid] = z4;   // 512 float4 = 2 x 1024 floats
        ((float4*)sH1b)[tid] = z4;
    }
    if (tid == 0) sSeen = 0;
    __syncthreads();   // last whole-CTA barrier

    if (warp >= 8) {
        // ================= group A: layer 0 (warps 8-15), unit u = warp-8 ==========
        const int u = warp - 8;
        float creg = 0.f;

        // register-resident W_hh0: wreg[g][j] = row (g*8+u), half2 #(j*32+lane)
        __half2 wreg[4][16];
#pragma unroll
        for (int g = 0; g < 4; g++) {
            const float2* src = (const float2*)(
                Whh0 + (size_t)(g * kNH + b * kUnitsPerCTA + u) * kNH);
#pragma unroll
            for (int j = 0; j < 16; j++) {
                float2 w = src[j * 32 + lane];
                wreg[g][j] = __floats2half2_rn(w.x, w.y);
            }
        }

        for (int e = 0; e < kT; e++) {
            // per-warp Z prefetch: lane g<4 loads gate-g preactivation of unit u
            float zl = 0.f;
            if (lane < 4)
                zl = Z0[(size_t)e * kNG + lane * kNH + b * kUnitsPerCTA + u];

            if (e > 0 && warp == 15) {
                // fused discovery+stage: poll the h0[e-1] DATA itself
                const float4* row = (const float4*)(H0 + (size_t)(e - 1) * kNH);
                float4 r0, r1, r2, r3, r4, r5, r6, r7;
                bool ok;
                do {
                    r0 = ld_vol4(row + 0 * 32 + lane);
                    r1 = ld_vol4(row + 1 * 32 + lane);
                    r2 = ld_vol4(row + 2 * 32 + lane);
                    r3 = ld_vol4(row + 3 * 32 + lane);
                    r4 = ld_vol4(row + 4 * 32 + lane);
                    r5 = ld_vol4(row + 5 * 32 + lane);
                    r6 = ld_vol4(row + 6 * 32 + lane);
                    r7 = ld_vol4(row + 7 * 32 + lane);
                    ok = ok4(r0) & ok4(r1) & ok4(r2) & ok4(r3)
                       & ok4(r4) & ok4(r5) & ok4(r6) & ok4(r7);
                } while (!__all_sync(0xffffffffu, ok));
                float4* d = (float4*)sH0a[e & 1];
                d[0 * 32 + lane] = r0; d[1 * 32 + lane] = r1;
                d[2 * 32 + lane] = r2; d[3 * 32 + lane] = r3;
                d[4 * 32 + lane] = r4; d[5 * 32 + lane] = r5;
                d[6 * 32 + lane] = r6; d[7 * 32 + lane] = r7;
                if (lane == 0)
                    asm volatile("st.release.cta.shared.u32 [%0], %1;"
                                 :: "r"(seenAddr), "r"(e) : "memory");
            }
            asm volatile("bar.sync 1, 256;" ::: "memory");   // sH0a[e&1] ready

            // matvec: 4 gate rows of unit u; weights in regs, h from SMEM
            const float2* hp = (const float2*)sH0a[e & 1];
            float s0 = 0.f, s1 = 0.f, s2 = 0.f, s3 = 0.f;
#pragma unroll
            for (int j = 0; j < 16; j++) {
                float2 hv = hp[j * 32 + lane];
                float2 w0 = __half22float2(wreg[0][j]);
                float2 w1 = __half22float2(wreg[1][j]);
                float2 w2 = __half22float2(wreg[2][j]);
                float2 w3 = __half22float2(wreg[3][j]);
                s0 = fmaf(w0.x, hv.x, fmaf(w0.y, hv.y, s0));
                s1 = fmaf(w1.x, hv.x, fmaf(w1.y, hv.y, s1));
                s2 = fmaf(w2.x, hv.x, fmaf(w2.y, hv.y, s2));
                s3 = fmaf(w3.x, hv.x, fmaf(w3.y, hv.y, s3));
            }
#pragma unroll
            for (int off = 16; off; off >>= 1) {
                s0 += __shfl_xor_sync(0xffffffffu, s0, off);
                s1 += __shfl_xor_sync(0xffffffffu, s1, off);
                s2 += __shfl_xor_sync(0xffffffffu, s2, off);
                s3 += __shfl_xor_sync(0xffffffffu, s3, off);
            }
            // in-warp activation (lane-uniform) and immediate publish
            float zi = s0 + __shfl_sync(0xffffffffu, zl, 0);
            float zf = s1 + __shfl_sync(0xffffffffu, zl, 1);
            float zg = s2 + __shfl_sync(0xffffffffu, zl, 2);
            float zo = s3 + __shfl_sync(0xffffffffu, zl, 3);
            float ig = 1.f / (1.f + __expf(-zi));
            float fg = 1.f / (1.f + __expf(-zf));
            float gg = 2.f / (1.f + __expf(-2.f * zg)) - 1.f;
            float og = 1.f / (1.f + __expf(-zo));
            creg = fmaf(fg, creg, ig * gg);
            float hval = og * (2.f / (1.f + __expf(-2.f * creg)) - 1.f);
            if (lane == 0)
                st_vol(H0 + (size_t)e * kNH + b * kUnitsPerCTA + u, hval);
        }
        // post-loop: prove h0[kT-1] complete so B's last epoch can proceed
        if (warp == 15) {
            const float4* row = (const float4*)(H0 + (size_t)(kT - 1) * kNH);
            bool ok;
            do {
                ok = true;
#pragma unroll
                for (int i = 0; i < 8; i++) ok &= ok4(ld_vol4(row + i * 32 + lane));
            } while (!__all_sync(0xffffffffu, ok));
            if (lane == 0)
                asm volatile("st.release.cta.shared.u32 [%0], %1;"
                             :: "r"(seenAddr), "r"(kT) : "memory");
        }
    } else {
        // ================= group B: layer 1 (warps 0-7), unit u = warp =============
        const int u = warp;
        float creg = 0.f;

        // register-resident W_ih1 rows (g*8+u)
        __half2 wih[4][16];
#pragma unroll
        for (int g = 0; g < 4; g++) {
            const float2* src = (const float2*)(
                Wih1 + (size_t)(g * kNH + b * kUnitsPerCTA + u) * kNH);
#pragma unroll
            for (int j = 0; j < 16; j++) {
                float2 w = src[j * 32 + lane];
                wih[g][j] = __floats2half2_rn(w.x, w.y);
            }
        }
        // W_hh1 row pointers (SMEM) and bias (lane-uniform)
        const __half2* wh0 = sW1h + (size_t)(0 * 8 + u) * 512;
        const __half2* wh1 = sW1h + (size_t)(1 * 8 + u) * 512;
        const __half2* wh2 = sW1h + (size_t)(2 * 8 + u) * 512;
        const __half2* wh3 = sW1h + (size_t)(3 * 8 + u) * 512;
        const float zb0 = sBias1[0 * 8 + u];
        const float zb1 = sBias1[1 * 8 + u];
        const float zb2 = sBias1[2 * 8 + u];
        const float zb3 = sBias1[3 * 8 + u];

        for (int e = 0; e < kT; e++) {
            if (warp < 7) {
                // layer-0 dep: SMEM mailbox spin (sSeen >= e+1 <=> h0[e] proven)
                int sv;
                do {
                    asm volatile("ld.acquire.cta.shared.u32 %0, [%1];"
                                 : "=r"(sv) : "r"(seenAddr) : "memory");
                } while (sv < e + 1);
                // stage h0[e] -> sH0b[e&1] (224 threads cover 256 float4)
                const float4* src = (const float4*)(H0 + (size_t)e * kNH);
                float4* dst = (float4*)sH0b[e & 1];
                int i0 = warp * 32 + lane;        // 0..223
                dst[i0] = ld_vol4(src + i0);
                if (i0 < 32) dst[i0 + 224] = ld_vol4(src + i0 + 224);
            } else if (e > 0) {
                // layer-1 dep: NaN-poll h1[e-1], fused with staging
                const float4* row = (const float4*)(H1 + (size_t)(e - 1) * kNH);
                float4 r0, r1, r2, r3, r4, r5, r6, r7;
                bool ok;
                do {
                    r0 = ld_vol4(row + 0 * 32 + lane);
                    r1 = ld_vol4(row + 1 * 32 + lane);
                    r2 = ld_vol4(row + 2 * 32 + lane);
                    r3 = ld_vol4(row + 3 * 32 + lane);
                    r4 = ld_vol4(row + 4 * 32 + lane);
                    r5 = ld_vol4(row + 5 * 32 + lane);
                    r6 = ld_vol4(row + 6 * 32 + lane);
                    r7 = ld_vol4(row + 7 * 32 + lane);
                    ok = ok4(r0) & ok4(r1) & ok4(r2) & ok4(r3)
                       & ok4(r4) & ok4(r5) & ok4(r6) & ok4(r7);
                } while (!__all_sync(0xffffffffu, ok));
                float4* d = (float4*)sH1b[e & 1];
                d[0 * 32 + lane] = r0; d[1 * 32 + lane] = r1;
                d[2 * 32 + lane] = r2; d[3 * 32 + lane] = r3;
                d[4 * 32 + lane] = r4; d[5 * 32 + lane] = r5;
                d[6 * 32 + lane] = r6; d[7 * 32 + lane] = r7;
            }
            asm volatile("bar.sync 2, 256;" ::: "memory");   // sH0b & sH1b ready

            // z1 = W_ih1(regs) @ h0[e] + W_hh1(SMEM) @ h1[e-1], 4 gate rows of unit u
            const float2* h0p = (const float2*)sH0b[e & 1];
            const float2* h1p = (const float2*)sH1b[e & 1];
            float s0 = 0.f, s1 = 0.f, s2 = 0.f, s3 = 0.f;
#pragma unroll
            for (int j = 0; j < 16; j++) {
                const int idx = j * 32 + lane;
                float2 hv = h0p[idx];
                float2 w0 = __half22float2(wih[0][j]);
                float2 w1 = __half22float2(wih[1][j]);
                float2 w2 = __half22float2(wih[2][j]);
                float2 w3 = __half22float2(wih[3][j]);
                s0 = fmaf(w0.x, hv.x, fmaf(w0.y, hv.y, s0));
                s1 = fmaf(w1.x, hv.x, fmaf(w1.y, hv.y, s1));
                s2 = fmaf(w2.x, hv.x, fmaf(w2.y, hv.y, s2));
                s3 = fmaf(w3.x, hv.x, fmaf(w3.y, hv.y, s3));
            }
#pragma unroll
            for (int j = 0; j < 16; j++) {
                const int idx = j * 32 + lane;
                float2 hv = h1p[idx];
                float2 w0 = __half22float2(wh0[idx]);
                float2 w1 = __half22float2(wh1[idx]);
                float2 w2 = __half22float2(wh2[idx]);
                float2 w3 = __half22float2(wh3[idx]);
                s0 = fmaf(w0.x, hv.x, fmaf(w0.y, hv.y, s0));
                s1 = fmaf(w1.x, hv.x, fmaf(w1.y, hv.y, s1));
                s2 = fmaf(w2.x, hv.x, fmaf(w2.y, hv.y, s2));
                s3 = fmaf(w3.x, hv.x, fmaf(w3.y, hv.y, s3));
            }
#pragma unroll
            for (int off = 16; off; off >>= 1) {
                s0 += __shfl_xor_sync(0xffffffffu, s0, off);
                s1 += __shfl_xor_sync(0xffffffffu, s1, off);
                s2 += __shfl_xor_sync(0xffffffffu, s2, off);
                s3 += __shfl_xor_sync(0xffffffffu, s3, off);
            }
            // in-warp activation and immediate publish
            float zi = s0 + zb0;
            float zf = s1 + zb1;
            float zg = s2 + zb2;
            float zo = s3 + zb3;
            float ig = 1.f / (1.f + __expf(-zi));
            float fg = 1.f / (1.f + __expf(-zf));
            float gg = 2.f / (1.f + __expf(-2.f * zg)) - 1.f;
            float og = 1.f / (1.f + __expf(-zo));
            creg = fmaf(fg, creg, ig * gg);
            float hval = og * (2.f / (1.f + __expf(-2.f * creg)) - 1.f);
            if (lane == 0)
                st_vol(H1 + (size_t)e * kNH + b * kUnitsPerCTA + u, hval);
        }
    }
}

// ---------------- softmax over NO=512 per row ----------------
__global__ __launch_bounds__(256) void softmax_rows(
    const float* __restrict__ L, float* __restrict__ out)
{
    __shared__ float red[256];
    int t = blockIdx.x, tid = threadIdx.x;
    const float* row = L + (size_t)t * kNO;
    float v0 = row[tid], v1 = row[tid + 256];
    float m = fmaxf(v0, v1);
    red[tid] = m; __syncthreads();
    for (int s = 128; s; s >>= 1) {
        if (tid < s) red[tid] = fmaxf(red[tid], red[tid + s]);
        __syncthreads();
    }
    m = red[0]; __syncthreads();
    float e0 = expf(v0 - m), e1 = expf(v1 - m);
    red[tid] = e0 + e1; __syncthreads();
    for (int s = 128; s; s >>= 1) {
        if (tid < s) red[tid] += red[tid + s];
        __syncthreads();
    }
    float inv = 1.f / red[0];
    out[(size_t)t * kNO + tid]       = e0 * inv;
    out[(size_t)t * kNO + tid + 256] = e1 * inv;
}

// ---------------- value head: out[t] = H1[t] . w_val + b_val ----------------
__global__ __launch_bounds__(256) void value_head(
    const float* __restrict__ H1, const float* __restrict__ wv,
    const float* __restrict__ bv, float* __restrict__ out)
{
    __shared__ float red[256];
    int t = blockIdx.x, tid = threadIdx.x;
    const float* h = H1 + (size_t)t * kNH;
    float s = 0.f;
    for (int k = tid; k < kNH; k += 256) s += h[k] * wv[k];
    red[tid] = s; __syncthreads();
    for (int r = 128; r; r >>= 1) {
        if (tid < r) red[tid] += red[tid + r];
        __syncthreads();
    }
    if (tid == 0) out[t] = red[0] + bv[0];
}

// ---------------- launch ----------------
extern "C" void kernel_launch(void* const* d_in, const int* in_sizes, int n_in,
                              void* d_out, int out_size)
{
    (void)in_sizes; (void)n_in; (void)out_size;
    const float* x     = (const float*)d_in[0];
    const float* w_ih0 = (const float*)d_in[1];
    const float* w_hh0 = (const float*)d_in[2];
    const float* b_ih0 = (const float*)d_in[3];
    const float* b_hh0 = (const float*)d_in[4];
    const float* w_ih1 = (const float*)d_in[5];
    const float* w_hh1 = (const float*)d_in[6];
    const float* b_ih1 = (const float*)d_in[7];
    const float* b_hh1 = (const float*)d_in[8];
    const float* w_pol = (const float*)d_in[9];
    const float* b_pol = (const float*)d_in[10];
    const float* w_val = (const float*)d_in[11];
    const float* b_val = (const float*)d_in[12];
    float* out = (float*)d_out;

    float *Z, *H0, *H1;
    cudaGetSymbolAddress((void**)&Z, g_Z);
    cudaGetSymbolAddress((void**)&H0, g_H0);
    cudaGetSymbolAddress((void**)&H1, g_H1);

    const int smem = 32 * 512 * (int)sizeof(__half2);  // 64 KB dynamic (W_hh1 only)
    cudaFuncSetAttribute(lstm_fused, cudaFuncAttributeMaxDynamicSharedMemorySize, smem);

    // NaN-canary prefill of H0/H1 (data-as-signal; replay-deterministic)
    const int n4 = kT * kNH / 4;  // 2M float4 per array
    prefill_nan<<<(n4 + 255) / 256, 256>>>((float4*)H0, n4);
    prefill_nan<<<(n4 + 255) / 256, 256>>>((float4*)H1, n4);

    // Z0 = X @ w_ih0^T + (b_ih0 + b_hh0)
    gemm_nt<<<dim3(kNG / 128, kT / 128), 256>>>(x, w_ih0, b_ih0, b_hh0, Z, kT, kNG, kNS);
    // fused 2-layer recurrence -> H0, H1
    lstm_fused<<<kNumCTA, 512, smem>>>(Z, w_hh0, w_ih1, w_hh1, b_ih1, b_hh1, H0, H1);
    // policy logits = H1 @ w_pol^T + b_pol (into Z scratch)
    gemm_nt<<<dim3(kNO / 128, kT / 128), 256>>>(H1, w_pol, b_pol, nullptr, Z, kT, kNO, kNH);
    // softmax -> out[0 : T*NO)
    softmax_rows<<<kT, 256>>>(Z, out);
    // value -> out[T*NO : T*NO + T)
    value_head<<<kT, 256>>>(H1, w_val, b_val, out + (size_t)kT * kNO);
}

// round 16
// speedup vs baseline: 2.7391x; 2.7391x over previous
#include <cuda_runtime.h>
#include <cuda_fp16.h>
#include <cstdint>

// Problem dims
constexpr int kT  = 8192;
constexpr int kNS = 512;
constexpr int kNH = 1024;
constexpr int kNO = 512;
constexpr int kNG = 4 * kNH;  // 4096 gate rows

constexpr int kNumCTA = 128;                 // persistent CTAs (<148 SMs -> co-resident)
constexpr int kUnitsPerCTA = kNH / kNumCTA;  // 8 hidden units per CTA

// ---------------- scratch (static device allocations; no cudaMalloc) ----------------
__device__ float g_Z[(size_t)kT * kNG];    // 128 MB: layer-0 gate preactivations / logits
__device__ float g_H0[(size_t)kT * kNH];   // 32 MB (NaN-canary protocol)
__device__ float g_H1[(size_t)kT * kNH];   // 32 MB (NaN-canary protocol)

// ---------------- NaN prefill: data-as-signal canary ----------------
__global__ void prefill_nan(float4* a, int n4) {
    int i = blockIdx.x * blockDim.x + threadIdx.x;
    const float qn = __int_as_float(0x7FC00000);
    float4 v = make_float4(qn, qn, qn, qn);
    if (i < n4) a[i] = v;
}

// ---------------- fp32 tiled GEMM: C[M,N] = A[M,K] * B[N,K]^T (+bias1[n]+bias2[n]) ----
__global__ __launch_bounds__(256) void gemm_nt(
    const float* __restrict__ A, const float* __restrict__ B,
    const float* __restrict__ b1, const float* __restrict__ b2,
    float* __restrict__ C, int M, int N, int K)
{
    __shared__ float As[8][128];
    __shared__ float Bs[8][128];
    const int tid = threadIdx.x;
    const int m0 = blockIdx.y * 128;
    const int n0 = blockIdx.x * 128;
    const int ty = tid >> 4;
    const int tx = tid & 15;
    const int lrow = tid >> 1;
    const int lk = (tid & 1) * 4;
    const float* Ap = A + (size_t)(m0 + lrow) * K + lk;
    const float* Bp = B + (size_t)(n0 + lrow) * K + lk;

    float acc[8][8];
#pragma unroll
    for (int i = 0; i < 8; i++)
#pragma unroll
        for (int j = 0; j < 8; j++) acc[i][j] = 0.f;

    for (int k0 = 0; k0 < K; k0 += 8) {
        float4 av = *(const float4*)(Ap + k0);
        float4 bv = *(const float4*)(Bp + k0);
        As[lk + 0][lrow] = av.x; As[lk + 1][lrow] = av.y;
        As[lk + 2][lrow] = av.z; As[lk + 3][lrow] = av.w;
        Bs[lk + 0][lrow] = bv.x; Bs[lk + 1][lrow] = bv.y;
        Bs[lk + 2][lrow] = bv.z; Bs[lk + 3][lrow] = bv.w;
        __syncthreads();
#pragma unroll
        for (int kk = 0; kk < 8; kk++) {
            float a[8], b[8];
#pragma unroll
            for (int i = 0; i < 8; i++) a[i] = As[kk][i * 16 + ty];
#pragma unroll
            for (int j = 0; j < 8; j++) b[j] = Bs[kk][j * 16 + tx];
#pragma unroll
            for (int i = 0; i < 8; i++)
#pragma unroll
                for (int j = 0; j < 8; j++) acc[i][j] += a[i] * b[j];
        }
        __syncthreads();
    }

#pragma unroll
    for (int j = 0; j < 8; j++) {
        int n = n0 + j * 16 + tx;
        float bias = 0.f;
        if (b1) bias += b1[n];
        if (b2) bias += b2[n];
#pragma unroll
        for (int i = 0; i < 8; i++) {
            int m = m0 + i * 16 + ty;
            C[(size_t)m * N + n] = acc[i][j] + bias;
        }
    }
}

// ---- helpers: volatile data-as-signal loads/stores ----
__device__ __forceinline__ float4 ld_vol4(const float4* p) {
    float4 v;
    asm volatile("ld.volatile.global.v4.f32 {%0,%1,%2,%3}, [%4];"
                 : "=f"(v.x), "=f"(v.y), "=f"(v.z), "=f"(v.w) : "l"(p) : "memory");
    return v;
}
__device__ __forceinline__ void st_vol(float* p, float v) {
    asm volatile("st.volatile.global.f32 [%0], %1;" :: "l"(p), "f"(v) : "memory");
}
__device__ __forceinline__ bool ok4(float4 v) {
    return (v.x == v.x) & (v.y == v.y) & (v.z == v.z) & (v.w == v.w);
}

// ---------------- fused 2-layer persistent LSTM recurrence -------------------------
// R12 structure (proven 21.7 ms) + distributed per-slice NaN-poll in group A.
// group A (warps 8-15): layer 0, W_hh0 rows in REGISTERS. ALL 8 warps poll their own
//   512B slice of h0[e-1] (traffic-neutral vs single-warp whole-row poll), stage
//   their registers into SMEM, then meet at the barrier. Publish: warp 15 only,
//   one coalesced 8-lane store. Parked warps wait at barriers, never spin.
// group B (warps 0-7): layer 1, W_ih1 in REGISTERS, W_hh1 in SMEM. Warp 7 polls the
//   mailbox + NaN-polls h1[e-1]; warps 0-6 WAIT AT THE BARRIER (no SMEM spin).
// NaN-canary protocol for cross-CTA handoff (see R11).
__global__ __launch_bounds__(512) void lstm_fused(
    const float* __restrict__ Z0, const float* __restrict__ Whh0,
    const float* __restrict__ Wih1, const float* __restrict__ Whh1,
    const float* __restrict__ b_ih1, const float* __restrict__ b_hh1,
    float* H0, float* H1)
{
    extern __shared__ __half2 sW1h[];            // [32][512] half2 = 64 KB (W_hh1 only)
    __shared__ float sH0a[kNH];
    __shared__ float sH0b[kNH];
    __shared__ float sH1b[kNH];
    __shared__ float sDotA[2][32];
    __shared__ float sDotB[2][32];
    __shared__ float sBias1[32];
    __shared__ int   sSeen;                      // mailbox: sSeen = e  <=>  h0[e-1] proven

    const int tid  = threadIdx.x;
    const int b    = blockIdx.x;
    const int warp = tid >> 5;
    const int lane = tid & 31;
    const uint32_t seenAddr = (uint32_t)__cvta_generic_to_shared(&sSeen);

    // ---- load + convert W_hh1 panel into SMEM (gate-major lr = g*8+u) ----
    for (int i = tid; i < 32 * 512; i += 512) {
        int lr = i >> 9, p = i & 511;
        int g = lr >> 3, u = lr & 7;
        const float2 wv = *(const float2*)(
            Whh1 + (size_t)(g * kNH + b * kUnitsPerCTA + u) * kNH + 2 * p);
        sW1h[i] = __floats2half2_rn(wv.x, wv.y);
    }
    if (tid < 32) {
        int g = tid >> 3, u = tid & 7;
        int idx = g * kNH + b * kUnitsPerCTA + u;
        sBias1[tid] = b_ih1[idx] + b_hh1[idx];
    }
    if (tid < 256) {
        ((float4*)sH0a)[tid] = make_float4(0.f, 0.f, 0.f, 0.f);
        ((float4*)sH1b)[tid] = make_float4(0.f, 0.f, 0.f, 0.f);
    }
    if (tid == 0) sSeen = 0;
    __syncthreads();   // last whole-CTA barrier

    if (warp >= 8) {
        // ================= group A: layer 0 (warps 8-15) =================
        const int wa = warp - 8;
        float creg = 0.f;

        // register-resident W_hh0 panel: wreg[r][j] = row (wa*4+r), half2 #(j*32+lane)
        __half2 wreg[4][16];
#pragma unroll
        for (int r = 0; r < 4; r++) {
            const int lr = wa * 4 + r;
            const int g = lr >> 3, u = lr & 7;
            const float2* src = (const float2*)(
                Whh0 + (size_t)(g * kNH + b * kUnitsPerCTA + u) * kNH);
#pragma unroll
            for (int j = 0; j < 16; j++) {
                float2 w = src[j * 32 + lane];
                wreg[r][j] = __floats2half2_rn(w.x, w.y);
            }
        }

        for (int e = 0; e < kT; e++) {
            float zv = 0.f;
            if (warp == 15)
                zv = Z0[(size_t)e * kNG + (lane >> 3) * kNH + b * kUnitsPerCTA + (lane & 7)];

            if (e > 0) {
                // distributed fused discovery+stage: each warp NaN-polls its own
                // 512B slice of h0[e-1] (index wa*32+lane), then stages it.
                const float4* row = (const float4*)(H0 + (size_t)(e - 1) * kNH);
                const int i0 = wa * 32 + lane;
                float4 r;
                do {
                    r = ld_vol4(row + i0);
                } while (!__all_sync(0xffffffffu, ok4(r)));
                ((float4*)sH0a)[i0] = r;
                asm volatile("bar.sync 1, 256;" ::: "memory");   // sH0a ready, row proven
                if (warp == 15 && lane == 0)
                    asm volatile("st.release.cta.shared.u32 [%0], %1;"
                                 :: "r"(seenAddr), "r"(e) : "memory");
            }

            // matvec: 4 rows/warp, weights from registers, h from SMEM
            const float2* sHp = (const float2*)sH0a;
            float s0 = 0.f, s1 = 0.f, s2 = 0.f, s3 = 0.f;
#pragma unroll
            for (int j = 0; j < 16; j++) {
                float2 hv = sHp[j * 32 + lane];
                float2 w0 = __half22float2(wreg[0][j]);
                float2 w1 = __half22float2(wreg[1][j]);
                float2 w2 = __half22float2(wreg[2][j]);
                float2 w3 = __half22float2(wreg[3][j]);
                s0 = fmaf(w0.x, hv.x, fmaf(w0.y, hv.y, s0));
                s1 = fmaf(w1.x, hv.x, fmaf(w1.y, hv.y, s1));
                s2 = fmaf(w2.x, hv.x, fmaf(w2.y, hv.y, s2));
                s3 = fmaf(w3.x, hv.x, fmaf(w3.y, hv.y, s3));
            }
#pragma unroll
            for (int off = 16; off; off >>= 1) {
                s0 += __shfl_xor_sync(0xffffffffu, s0, off);
                s1 += __shfl_xor_sync(0xffffffffu, s1, off);
                s2 += __shfl_xor_sync(0xffffffffu, s2, off);
                s3 += __shfl_xor_sync(0xffffffffu, s3, off);
            }
            if (lane == 0) {
                float* d = &sDotA[e & 1][wa * 4];
                d[0] = s0; d[1] = s1; d[2] = s2; d[3] = s3;
            }
            asm volatile("bar.sync 1, 256;" ::: "memory");

            if (warp == 15) {
                float z = sDotA[e & 1][lane] + zv;
                const bool isg = (lane >= 16) & (lane < 24);
                const float sm = isg ? 2.f : 1.f;
                float sig = 1.f / (1.f + __expf(-sm * z));
                float a = isg ? fmaf(sig, 2.f, -1.f) : sig;
                const int u = lane & 7;
                float i_ = __shfl_sync(0xffffffffu, a, u);
                float f_ = __shfl_sync(0xffffffffu, a, 8 + u);
                float g_ = __shfl_sync(0xffffffffu, a, 16 + u);
                float o_ = __shfl_sync(0xffffffffu, a, 24 + u);
                if (lane < kUnitsPerCTA) {
                    creg = fmaf(f_, creg, i_ * g_);
                    float tc = 2.f / (1.f + __expf(-2.f * creg)) - 1.f;
                    // publish: one coalesced 8-lane store (data IS the signal)
                    st_vol(H0 + (size_t)e * kNH + b * kUnitsPerCTA + lane, o_ * tc);
                }
            }
        }
        // post-loop: prove h0[kT-1] complete so B's last epoch can proceed
        if (warp == 15) {
            const float4* row = (const float4*)(H0 + (size_t)(kT - 1) * kNH);
            bool ok;
            do {
                ok = true;
#pragma unroll
                for (int i = 0; i < 8; i++) ok &= ok4(ld_vol4(row + i * 32 + lane));
            } while (!__all_sync(0xffffffffu, ok));
            if (lane == 0)
                asm volatile("st.release.cta.shared.u32 [%0], %1;"
                             :: "r"(seenAddr), "r"(kT) : "memory");
        }
    } else {
        // ================= group B: layer 1 (warps 0-7) =================
        const int wb = warp;
        const int tb = tid;                            // 0..255 within group
        const __half2* wHh = sW1h + (size_t)(wb * 4) * 512;
        float creg = 0.f;
        const float bias = sBias1[lane];

        // register-resident W_ih1 panel
        __half2 wreg[4][16];
#pragma unroll
        for (int r = 0; r < 4; r++) {
            const int lr = wb * 4 + r;
            const int g = lr >> 3, u = lr & 7;
            const float2* src = (const float2*)(
                Wih1 + (size_t)(g * kNH + b * kUnitsPerCTA + u) * kNH);
#pragma unroll
            for (int j = 0; j < 16; j++) {
                float2 w = src[j * 32 + lane];
                wreg[r][j] = __floats2half2_rn(w.x, w.y);
            }
        }

        for (int e = 0; e < kT; e++) {
            if (warp == 7) {
                // layer-0 dep: mailbox (sSeen >= e+1  <=>  h0[e] proven visible).
                // ONLY warp 7 spins; warps 0-6 are parked at the barrier below.
                int sv;
                do {
                    asm volatile("ld.acquire.cta.shared.u32 %0, [%1];"
                                 : "=r"(sv) : "r"(seenAddr) : "memory");
                } while (sv < e + 1);
                // layer-1 dep: NaN-poll h1[e-1] data, fused with staging
                if (e > 0) {
                    const float4* row = (const float4*)(H1 + (size_t)(e - 1) * kNH);
                    float4 r0, r1, r2, r3, r4, r5, r6, r7;
                    bool ok;
                    do {
                        r0 = ld_vol4(row + 0 * 32 + lane);
                        r1 = ld_vol4(row + 1 * 32 + lane);
                        r2 = ld_vol4(row + 2 * 32 + lane);
                        r3 = ld_vol4(row + 3 * 32 + lane);
                        r4 = ld_vol4(row + 4 * 32 + lane);
                        r5 = ld_vol4(row + 5 * 32 + lane);
                        r6 = ld_vol4(row + 6 * 32 + lane);
                        r7 = ld_vol4(row + 7 * 32 + lane);
                        ok = ok4(r0) & ok4(r1) & ok4(r2) & ok4(r3)
                           & ok4(r4) & ok4(r5) & ok4(r6) & ok4(r7);
                    } while (!__all_sync(0xffffffffu, ok));
                    float4* d = (float4*)sH1b;
                    d[0 * 32 + lane] = r0; d[1 * 32 + lane] = r1;
                    d[2 * 32 + lane] = r2; d[3 * 32 + lane] = r3;
                    d[4 * 32 + lane] = r4; d[5 * 32 + lane] = r5;
                    d[6 * 32 + lane] = r6; d[7 * 32 + lane] = r7;
                }
            }
            asm volatile("bar.sync 2, 256;" ::: "memory");
            // stage h0[e] (proven visible via mailbox)
            ((float4*)sH0b)[tb] = ld_vol4((const float4*)(H0 + (size_t)e * kNH) + tb);
            asm volatile("bar.sync 2, 256;" ::: "memory");

            // z1 = W_ih1(regs) @ h0[e] + W_hh1(SMEM) @ h1[e-1], 4 rows/warp
            const float2* h0p = (const float2*)sH0b;
            const float2* h1p = (const float2*)sH1b;
            float s0 = 0.f, s1 = 0.f, s2 = 0.f, s3 = 0.f;
#pragma unroll
            for (int j = 0; j < 16; j++) {
                float2 hv = h0p[j * 32 + lane];
                float2 w0 = __half22float2(wreg[0][j]);
                float2 w1 = __half22float2(wreg[1][j]);
                float2 w2 = __half22float2(wreg[2][j]);
                float2 w3 = __half22float2(wreg[3][j]);
                s0 = fmaf(w0.x, hv.x, fmaf(w0.y, hv.y, s0));
                s1 = fmaf(w1.x, hv.x, fmaf(w1.y, hv.y, s1));
                s2 = fmaf(w2.x, hv.x, fmaf(w2.y, hv.y, s2));
                s3 = fmaf(w3.x, hv.x, fmaf(w3.y, hv.y, s3));
            }
#pragma unroll
            for (int j = 0; j < 16; j++) {
                const int idx = j * 32 + lane;
                float2 hv = h1p[idx];
                float2 w0 = __half22float2(wHh[idx]);
                float2 w1 = __half22float2(wHh[512 + idx]);
                float2 w2 = __half22float2(wHh[1024 + idx]);
                float2 w3 = __half22float2(wHh[1536 + idx]);
                s0 = fmaf(w0.x, hv.x, fmaf(w0.y, hv.y, s0));
                s1 = fmaf(w1.x, hv.x, fmaf(w1.y, hv.y, s1));
                s2 = fmaf(w2.x, hv.x, fmaf(w2.y, hv.y, s2));
                s3 = fmaf(w3.x, hv.x, fmaf(w3.y, hv.y, s3));
            }
#pragma unroll
            for (int off = 16; off; off >>= 1) {
                s0 += __shfl_xor_sync(0xffffffffu, s0, off);
                s1 += __shfl_xor_sync(0xffffffffu, s1, off);
                s2 += __shfl_xor_sync(0xffffffffu, s2, off);
                s3 += __shfl_xor_sync(0xffffffffu, s3, off);
            }
            if (lane == 0) {
                float* d = &sDotB[e & 1][wb * 4];
                d[0] = s0; d[1] = s1; d[2] = s2; d[3] = s3;
            }
            asm volatile("bar.sync 2, 256;" ::: "memory");

            if (warp == 7) {
                float z = sDotB[e & 1][lane] + bias;
                const bool isg = (lane >= 16) & (lane < 24);
                const float sm = isg ? 2.f : 1.f;
                float sig = 1.f / (1.f + __expf(-sm * z));
                float a = isg ? fmaf(sig, 2.f, -1.f) : sig;
                const int u = lane & 7;
                float i_ = __shfl_sync(0xffffffffu, a, u);
                float f_ = __shfl_sync(0xffffffffu, a, 8 + u);
                float g_ = __shfl_sync(0xffffffffu, a, 16 + u);
                float o_ = __shfl_sync(0xffffffffu, a, 24 + u);
                if (lane < kUnitsPerCTA) {
                    creg = fmaf(f_, creg, i_ * g_);
                    float tc = 2.f / (1.f + __expf(-2.f * creg)) - 1.f;
                    st_vol(H1 + (size_t)e * kNH + b * kUnitsPerCTA + lane, o_ * tc);
                }
            }
        }
    }
}

// ---------------- softmax over NO=512 per row ----------------
__global__ __launch_bounds__(256) void softmax_rows(
    const float* __restrict__ L, float* __restrict__ out)
{
    __shared__ float red[256];
    int t = blockIdx.x, tid = threadIdx.x;
    const float* row = L + (size_t)t * kNO;
    float v0 = row[tid], v1 = row[tid + 256];
    float m = fmaxf(v0, v1);
    red[tid] = m; __syncthreads();
    for (int s = 128; s; s >>= 1) {
        if (tid < s) red[tid] = fmaxf(red[tid], red[tid + s]);
        __syncthreads();
    }
    m = red[0]; __syncthreads();
    float e0 = expf(v0 - m), e1 = expf(v1 - m);
    red[tid] = e0 + e1; __syncthreads();
    for (int s = 128; s; s >>= 1) {
        if (tid < s) red[tid] += red[tid + s];
        __syncthreads();
    }
    float inv = 1.f / red[0];
    out[(size_t)t * kNO + tid]       = e0 * inv;
    out[(size_t)t * kNO + tid + 256] = e1 * inv;
}

// ---------------- value head: out[t] = H1[t] . w_val + b_val ----------------
__global__ __launch_bounds__(256) void value_head(
    const float* __restrict__ H1, const float* __restrict__ wv,
    const float* __restrict__ bv, float* __restrict__ out)
{
    __shared__ float red[256];
    int t = blockIdx.x, tid = threadIdx.x;
    const float* h = H1 + (size_t)t * kNH;
    float s = 0.f;
    for (int k = tid; k < kNH; k += 256) s += h[k] * wv[k];
    red[tid] = s; __syncthreads();
    for (int r = 128; r; r >>= 1) {
        if (tid < r) red[tid] += red[tid + r];
        __syncthreads();
    }
    if (tid == 0) out[t] = red[0] + bv[0];
}

// ---------------- launch ----------------
extern "C" void kernel_launch(void* const* d_in, const int* in_sizes, int n_in,
                              void* d_out, int out_size)
{
    (void)in_sizes; (void)n_in; (void)out_size;
    const float* x     = (const float*)d_in[0];
    const float* w_ih0 = (const float*)d_in[1];
    const float* w_hh0 = (const float*)d_in[2];
    const float* b_ih0 = (const float*)d_in[3];
    const float* b_hh0 = (const float*)d_in[4];
    const float* w_ih1 = (const float*)d_in[5];
    const float* w_hh1 = (const float*)d_in[6];
    const float* b_ih1 = (const float*)d_in[7];
    const float* b_hh1 = (const float*)d_in[8];
    const float* w_pol = (const float*)d_in[9];
    const float* b_pol = (const float*)d_in[10];
    const float* w_val = (const float*)d_in[11];
    const float* b_val = (const float*)d_in[12];
    float* out = (float*)d_out;

    float *Z, *H0, *H1;
    cudaGetSymbolAddress((void**)&Z, g_Z);
    cudaGetSymbolAddress((void**)&H0, g_H0);
    cudaGetSymbolAddress((void**)&H1, g_H1);

    const int smem = 32 * 512 * (int)sizeof(__half2);  // 64 KB dynamic (W_hh1 only)
    cudaFuncSetAttribute(lstm_fused, cudaFuncAttributeMaxDynamicSharedMemorySize, smem);

    // NaN-canary prefill of H0/H1 (data-as-signal; replay-deterministic)
    const int n4 = kT * kNH / 4;  // 2M float4 per array
    prefill_nan<<<(n4 + 255) / 256, 256>>>((float4*)H0, n4);
    prefill_nan<<<(n4 + 255) / 256, 256>>>((float4*)H1, n4);

    // Z0 = X @ w_ih0^T + (b_ih0 + b_hh0)
    gemm_nt<<<dim3(kNG / 128, kT / 128), 256>>>(x, w_ih0, b_ih0, b_hh0, Z, kT, kNG, kNS);
    // fused 2-layer recurrence -> H0, H1
    lstm_fused<<<kNumCTA, 512, smem>>>(Z, w_hh0, w_ih1, w_hh1, b_ih1, b_hh1, H0, H1);
    // policy logits = H1 @ w_pol^T + b_pol (into Z scratch)
    gemm_nt<<<dim3(kNO / 128, kT / 128), 256>>>(H1, w_pol, b_pol, nullptr, Z, kT, kNO, kNH);
    // softmax -> out[0 : T*NO)
    softmax_rows<<<kT, 256>>>(Z, out);
    // value -> out[T*NO : T*NO + T)
    value_head<<<kT, 256>>>(H1, w_val, b_val, out + (size_t)kT * kNO);
}